// round 1
// baseline (speedup 1.0000x reference)
#include <cuda_runtime.h>
#include <cstdint>

// Problem constants
#define B_    4
#define L_    1024
#define V_    1280
#define E_    768
#define NBIN  8
#define NHID  32

// Output layout: concat(logits[B,L,8,V], tte[B,L,V], mask[B,L,8,V]) fp32
#define LOGITS_OFF 0
#define TTE_OFF    ((size_t)B_ * L_ * NBIN * V_)                 // 41943040
#define MASK_OFF   (TTE_OFF + (size_t)B_ * L_ * V_)              // 47185920

// Scratch for x = h @ W1 : (B*L, 256) fp32 = 4 MB (device global, no alloc)
__device__ float g_x[(size_t)B_ * L_ * NBIN * NHID];

// ---------------------------------------------------------------------------
// Kernel 1: x = h @ W1   (M=4096, K=768, N=256)  classic tiled SGEMM
// ---------------------------------------------------------------------------
__global__ __launch_bounds__(256) void k_gemm1(const float* __restrict__ A,
                                               const float* __restrict__ W1) {
    __shared__ float As[16][64 + 4];
    __shared__ float Bs[16][64 + 4];
    const int K = E_, N = NBIN * NHID;  // 768, 256
    int bx = blockIdx.x;                 // 0..3   (N / 64)
    int by = blockIdx.y;                 // 0..63  (M / 64)
    int tid = threadIdx.x;
    int tx = tid & 15, ty = tid >> 4;
    int rowBase = by * 64, colBase = bx * 64;

    float acc[4][4];
#pragma unroll
    for (int i = 0; i < 4; i++)
#pragma unroll
        for (int j = 0; j < 4; j++) acc[i][j] = 0.0f;

    for (int k0 = 0; k0 < K; k0 += 16) {
#pragma unroll
        for (int i = 0; i < 4; i++) {
            int idx = tid + i * 256;        // over 64x16 A tile
            int r = idx >> 4, c = idx & 15;
            As[c][r] = A[(size_t)(rowBase + r) * K + k0 + c];
        }
#pragma unroll
        for (int i = 0; i < 4; i++) {
            int idx = tid + i * 256;        // over 16x64 B tile
            int r = idx >> 6, c = idx & 63;
            Bs[r][c] = W1[(size_t)(k0 + r) * N + colBase + c];
        }
        __syncthreads();
#pragma unroll
        for (int kk = 0; kk < 16; kk++) {
            float a[4], b[4];
#pragma unroll
            for (int i = 0; i < 4; i++) a[i] = As[kk][ty * 4 + i];
#pragma unroll
            for (int j = 0; j < 4; j++) b[j] = Bs[kk][tx * 4 + j];
#pragma unroll
            for (int i = 0; i < 4; i++)
#pragma unroll
                for (int j = 0; j < 4; j++) acc[i][j] += a[i] * b[j];
        }
        __syncthreads();
    }
#pragma unroll
    for (int i = 0; i < 4; i++)
#pragma unroll
        for (int j = 0; j < 4; j++)
            g_x[(size_t)(rowBase + ty * 4 + i) * N + colBase + tx * 4 + j] = acc[i][j];
}

// ---------------------------------------------------------------------------
// Kernel 2: tte + censor_mask.
// next-occurrence suffix scan per (b, v), chunked over i for parallelism.
// Special case (from the scatter semantics): token_index[b, i>=1, v=0] = 0.
// ---------------------------------------------------------------------------
__global__ __launch_bounds__(128) void k_tte_mask(const int* __restrict__ targets,
                                                  const float* __restrict__ age,
                                                  const float* __restrict__ targets_age,
                                                  float* __restrict__ out) {
    __shared__ int   tg[L_];
    __shared__ float ag[L_];
    __shared__ float ta[L_];

    int b     = blockIdx.z;                 // 0..3
    int chunk = blockIdx.y;                 // 0..7 (i-chunks of 128)
    int v     = blockIdx.x * 128 + threadIdx.x;  // 0..1279

    for (int i = threadIdx.x; i < L_; i += 128) {
        tg[i] = targets[(size_t)b * L_ + i];
        ag[i] = age[(size_t)b * L_ + i];
        ta[i] = targets_age[(size_t)b * L_ + i];
    }
    __syncthreads();

    float* out_tte  = out + TTE_OFF  + (size_t)b * L_ * V_;
    float* out_mask = out + MASK_OFF + (size_t)b * L_ * NBIN * V_;

    int i0  = chunk * 128;
    int nxt = L_;   // next index j >= i with targets[j] == v
    for (int i = L_ - 1; i >= i0; --i) {
        if (tg[i] == v) nxt = i;
        if (i < i0 + 128) {
            int idx = (v == 0 && i >= 1) ? 0 : nxt;
            bool noev = (idx == L_);
            int idxc = noev ? (L_ - 1) : idx;
            float tte = ta[idxc] - ag[i];
            out_tte[(size_t)i * V_ + v] = tte;
            size_t mbase = (size_t)i * NBIN * V_ + v;
#pragma unroll
            for (int n = 0; n < NBIN; n++) {
                float lo = 1.25f * n;
                float hi = 1.25f * (n + 1);
                bool m = (tte >= lo && tte < hi) || noev;
                out_mask[mbase + (size_t)n * V_] = m ? 1.0f : 0.0f;
            }
        }
    }
}

// ---------------------------------------------------------------------------
// Kernel 3: logits = x @ W2 per bin  (M = B*L rows, per row: 8 bins x 1280 v,
// K = 32).  Block = 8 rows, thread = one v (5 iterations over v).
// W2 column held in 32 registers; x read via broadcast LDS.128 (1 LDS : 4 FMA).
// ---------------------------------------------------------------------------
#define R3 8
__global__ __launch_bounds__(256) void k_gemm2(const float* __restrict__ W2,
                                               float* __restrict__ out) {
    __shared__ float4 xs[R3][64];   // 8 rows x 256 floats
    int rowBase = blockIdx.x * R3;  // row index into (B*L)

    const float* xsrc = g_x + (size_t)rowBase * 256;
    float* xsF = (float*)xs;
    for (int i = threadIdx.x; i < R3 * 256; i += 256) xsF[i] = xsrc[i];
    __syncthreads();

    for (int it = 0; it < 5; ++it) {
        int v = it * 256 + threadIdx.x;
        float w2[32];
#pragma unroll
        for (int h = 0; h < 32; h++) w2[h] = W2[(size_t)h * V_ + v];

        for (int r = 0; r < R3; r++) {
            float acc[NBIN];
#pragma unroll
            for (int n = 0; n < NBIN; n++) acc[n] = 0.0f;
#pragma unroll
            for (int h4 = 0; h4 < 8; h4++) {
#pragma unroll
                for (int n = 0; n < NBIN; n++) {
                    float4 xv = xs[r][n * 8 + h4];
                    acc[n] += xv.x * w2[h4 * 4 + 0];
                    acc[n] += xv.y * w2[h4 * 4 + 1];
                    acc[n] += xv.z * w2[h4 * 4 + 2];
                    acc[n] += xv.w * w2[h4 * 4 + 3];
                }
            }
            size_t obase = (size_t)(rowBase + r) * NBIN * V_ + v;
#pragma unroll
            for (int n = 0; n < NBIN; n++)
                out[obase + (size_t)n * V_] = acc[n];
        }
    }
}

// ---------------------------------------------------------------------------
extern "C" void kernel_launch(void* const* d_in, const int* in_sizes, int n_in,
                              void* d_out, int out_size) {
    const float* h       = (const float*)d_in[0];  // (B,L,768)
    const float* age     = (const float*)d_in[1];  // (B,L)
    const float* tage    = (const float*)d_in[2];  // (B,L)
    // d_in[3] = delta_t (unused by the outputs)
    const int*   targets = (const int*)d_in[4];    // (B,L) int32
    const float* W1      = (const float*)d_in[5];  // (768,256)
    const float* W2      = (const float*)d_in[6];  // (32,1280)
    float* out = (float*)d_out;

    k_gemm1<<<dim3(4, 64), 256>>>(h, W1);
    k_tte_mask<<<dim3(10, 8, B_), 128>>>(targets, age, tage, out);
    k_gemm2<<<(B_ * L_) / R3, 256>>>(W2, out);
}

// round 3
// speedup vs baseline: 1.1864x; 1.1864x over previous
#include <cuda_runtime.h>
#include <cstdint>

// Problem constants
#define B_    4
#define L_    1024
#define V_    1280
#define E_    768
#define NBIN  8
#define NHID  32

// Output layout: concat(logits[B,L,8,V], tte[B,L,V], mask[B,L,8,V]) fp32
#define LOGITS_OFF 0
#define TTE_OFF    ((size_t)B_ * L_ * NBIN * V_)                 // 41943040
#define MASK_OFF   (TTE_OFF + (size_t)B_ * L_ * V_)              // 47185920

// Scratch for x = h @ W1 : (B*L, 256) fp32, stored TRANSPOSED per row:
// g_x[row*256 + h*8 + n]  (h = hidden 0..31, n = bin 0..7)
__device__ float g_x[(size_t)B_ * L_ * NBIN * NHID];

typedef unsigned long long u64;

union F4U2 { float4 f; u64 u[2]; };

__device__ __forceinline__ u64 pk(float lo, float hi) {
    u64 r; asm("mov.b64 %0, {%1,%2};" : "=l"(r) : "f"(lo), "f"(hi)); return r;
}
__device__ __forceinline__ void upk(u64 v, float& lo, float& hi) {
    asm("mov.b64 {%0,%1}, %2;" : "=f"(lo), "=f"(hi) : "l"(v));
}
__device__ __forceinline__ void fma2(u64& d, u64 a, u64 b) {
    asm("fma.rn.f32x2 %0, %1, %2, %0;" : "+l"(d) : "l"(a), "l"(b));
}

// ---------------------------------------------------------------------------
// Kernel 1: x = h @ W1   (M=4096, K=768, N=256)  tiled SGEMM with f32x2.
// 64x64 tile, 256 threads, 4x4 per thread via diagonal-packed FFMA2.
// Writes g_x in transposed [h][bin] per-row layout for gemm2.
// ---------------------------------------------------------------------------
__global__ __launch_bounds__(256) void k_gemm1(const float* __restrict__ A,
                                               const float* __restrict__ W1) {
    __shared__ float As[16][68];
    __shared__ float Bs[16][68];
    const int K = E_, N = NBIN * NHID;  // 768, 256
    int bx = blockIdx.x;                 // 0..3   (N / 64)
    int by = blockIdx.y;                 // 0..63  (M / 64)
    int tid = threadIdx.x;
    int tx = tid & 15, ty = tid >> 4;
    int rowBase = by * 64, colBase = bx * 64;

    u64 c0 = 0, c1 = 0, c2 = 0, c3 = 0, c4 = 0, c5 = 0, c6 = 0, c7 = 0;

    for (int k0 = 0; k0 < K; k0 += 16) {
#pragma unroll
        for (int i = 0; i < 4; i++) {
            int idx = tid + i * 256;        // over 64x16 A tile
            int r = idx >> 4, c = idx & 15;
            As[c][r] = A[(size_t)(rowBase + r) * K + k0 + c];
        }
#pragma unroll
        for (int i = 0; i < 4; i++) {
            int idx = tid + i * 256;        // over 16x64 B tile
            int r = idx >> 6, c = idx & 63;
            Bs[r][c] = W1[(size_t)(k0 + r) * N + colBase + c];
        }
        __syncthreads();
#pragma unroll
        for (int kk = 0; kk < 16; kk++) {
            F4U2 av, bv;
            av.f = *(const float4*)&As[kk][ty * 4];
            bv.f = *(const float4*)&Bs[kk][tx * 4];
            u64 a01 = av.u[0], a23 = av.u[1];
            u64 b01 = bv.u[0], b23 = bv.u[1];
            u64 b12 = pk(bv.f.y, bv.f.z);
            u64 b30 = pk(bv.f.w, bv.f.x);
            fma2(c0, a01, b01);   // (0,0) (1,1)
            fma2(c1, a01, b12);   // (0,1) (1,2)
            fma2(c2, a01, b23);   // (0,2) (1,3)
            fma2(c3, a01, b30);   // (0,3) (1,0)
            fma2(c4, a23, b01);   // (2,0) (3,1)
            fma2(c5, a23, b12);   // (2,1) (3,2)
            fma2(c6, a23, b23);   // (2,2) (3,3)
            fma2(c7, a23, b30);   // (2,3) (3,0)
        }
        __syncthreads();
    }

    // Unpack diagonal pairs into o[i][j]
    float o[4][4];
    upk(c0, o[0][0], o[1][1]);
    upk(c1, o[0][1], o[1][2]);
    upk(c2, o[0][2], o[1][3]);
    upk(c3, o[0][3], o[1][0]);
    upk(c4, o[2][0], o[3][1]);
    upk(c5, o[2][1], o[3][2]);
    upk(c6, o[2][2], o[3][3]);
    upk(c7, o[2][3], o[3][0]);

#pragma unroll
    for (int i = 0; i < 4; i++) {
        size_t rbase = (size_t)(rowBase + ty * 4 + i) * 256;
#pragma unroll
        for (int j = 0; j < 4; j++) {
            int c = colBase + tx * 4 + j;           // original col = n*32+h
            int pc = (c & 31) * 8 + (c >> 5);       // transposed [h][n]
            g_x[rbase + pc] = o[i][j];
        }
    }
}

// ---------------------------------------------------------------------------
// Kernel 2: tte + censor_mask.  2 v per thread, float2 stores.
// Special case (scatter semantics): token_index[b, i>=1, v=0] = 0.
// ---------------------------------------------------------------------------
__global__ __launch_bounds__(128) void k_tte_mask(const int* __restrict__ targets,
                                                  const float* __restrict__ age,
                                                  const float* __restrict__ targets_age,
                                                  float* __restrict__ out) {
    __shared__ int   tg[L_];
    __shared__ float ag[L_];
    __shared__ float ta[L_];

    int b     = blockIdx.z;                          // 0..3
    int chunk = blockIdx.y;                          // 0..7 (i-chunks of 128)
    int v0    = 2 * (blockIdx.x * 128 + threadIdx.x);  // even v in [0,1280)
    int v1    = v0 + 1;

    for (int i = threadIdx.x; i < L_; i += 128) {
        tg[i] = targets[(size_t)b * L_ + i];
        ag[i] = age[(size_t)b * L_ + i];
        ta[i] = targets_age[(size_t)b * L_ + i];
    }
    __syncthreads();

    float* out_tte  = out + TTE_OFF  + (size_t)b * L_ * V_;
    float* out_mask = out + MASK_OFF + (size_t)b * L_ * NBIN * V_;

    int i0   = chunk * 128;
    int nxt0 = L_, nxt1 = L_;
    for (int i = L_ - 1; i >= i0; --i) {
        int t = tg[i];
        if (t == v0) nxt0 = i;
        if (t == v1) nxt1 = i;
        if (i < i0 + 128) {
            int idx0 = (v0 == 0 && i >= 1) ? 0 : nxt0;
            int idx1 = nxt1;
            bool ne0 = (idx0 == L_);
            bool ne1 = (idx1 == L_);
            float a = ag[i];
            float t0 = ta[ne0 ? (L_ - 1) : idx0] - a;
            float t1 = ta[ne1 ? (L_ - 1) : idx1] - a;
            *(float2*)&out_tte[(size_t)i * V_ + v0] = make_float2(t0, t1);
            size_t mbase = (size_t)i * NBIN * V_ + v0;
#pragma unroll
            for (int n = 0; n < NBIN; n++) {
                float lo = 1.25f * n;
                float hi = 1.25f * (n + 1);
                float m0 = ((t0 >= lo && t0 < hi) || ne0) ? 1.0f : 0.0f;
                float m1 = ((t1 >= lo && t1 < hi) || ne1) ? 1.0f : 0.0f;
                *(float2*)&out_mask[mbase + (size_t)n * V_] = make_float2(m0, m1);
            }
        }
    }
}

// ---------------------------------------------------------------------------
// Kernel 3: logits = x @ W2 per bin.  Block = 8 rows, thread = one v.
// xs holds rows in transposed [h][bin] layout -> bin pairs are contiguous u64,
// multiplied by replicated w2 via FFMA2 (2x fma-pipe throughput).
// ---------------------------------------------------------------------------
#define R3 8
__global__ __launch_bounds__(256) void k_gemm2(const float* __restrict__ W2,
                                               float* __restrict__ out) {
    __shared__ float xs[R3][256];   // 8 rows x 256 floats ([h][bin] layout)
    int rowBase = blockIdx.x * R3;

    const float4* xsrc = (const float4*)(g_x + (size_t)rowBase * 256);
    float4* xsF = (float4*)xs;
#pragma unroll
    for (int i = 0; i < 2; i++) xsF[threadIdx.x + i * 256] = xsrc[threadIdx.x + i * 256];
    __syncthreads();

    for (int it = 0; it < 5; ++it) {
        int v = it * 256 + threadIdx.x;
        u64 w2r[32];
#pragma unroll
        for (int h = 0; h < 32; h++) {
            float w = W2[(size_t)h * V_ + v];
            w2r[h] = pk(w, w);
        }

        for (int r = 0; r < R3; r++) {
            u64 acc0 = 0, acc1 = 0, acc2 = 0, acc3 = 0;  // bin pairs (0,1)(2,3)(4,5)(6,7)
#pragma unroll
            for (int h = 0; h < 32; h++) {
                F4U2 qa, qb;
                qa.f = *(const float4*)&xs[r][h * 8];
                qb.f = *(const float4*)&xs[r][h * 8 + 4];
                fma2(acc0, qa.u[0], w2r[h]);
                fma2(acc1, qa.u[1], w2r[h]);
                fma2(acc2, qb.u[0], w2r[h]);
                fma2(acc3, qb.u[1], w2r[h]);
            }
            float o[8];
            upk(acc0, o[0], o[1]);
            upk(acc1, o[2], o[3]);
            upk(acc2, o[4], o[5]);
            upk(acc3, o[6], o[7]);
            size_t obase = (size_t)(rowBase + r) * NBIN * V_ + v;
#pragma unroll
            for (int n = 0; n < NBIN; n++)
                out[obase + (size_t)n * V_] = o[n];
        }
    }
}

// ---------------------------------------------------------------------------
static cudaStream_t g_s2;
static cudaEvent_t g_e1, g_e2;
static struct StreamInit {
    StreamInit() {
        cudaStreamCreateWithFlags(&g_s2, cudaStreamNonBlocking);
        cudaEventCreateWithFlags(&g_e1, cudaEventDisableTiming);
        cudaEventCreateWithFlags(&g_e2, cudaEventDisableTiming);
    }
} g_stream_init;

extern "C" void kernel_launch(void* const* d_in, const int* in_sizes, int n_in,
                              void* d_out, int out_size) {
    const float* h       = (const float*)d_in[0];  // (B,L,768)
    const float* age     = (const float*)d_in[1];  // (B,L)
    const float* tage    = (const float*)d_in[2];  // (B,L)
    // d_in[3] = delta_t (unused by the outputs)
    const int*   targets = (const int*)d_in[4];    // (B,L) int32
    const float* W1      = (const float*)d_in[5];  // (768,256)
    const float* W2      = (const float*)d_in[6];  // (32,1280)
    float* out = (float*)d_out;

    // Fork: tte/mask (store-bound) overlaps the two GEMMs (fma-bound).
    cudaEventRecord(g_e1, 0);
    cudaStreamWaitEvent(g_s2, g_e1, 0);
    k_tte_mask<<<dim3(5, 8, B_), 128, 0, g_s2>>>(targets, age, tage, out);

    k_gemm1<<<dim3(4, 64), 256>>>(h, W1);
    k_gemm2<<<(B_ * L_) / R3, 256>>>(W2, out);

    cudaEventRecord(g_e2, g_s2);
    cudaStreamWaitEvent(0, g_e2, 0);
}